// round 1
// baseline (speedup 1.0000x reference)
#include <cuda_runtime.h>
#include <math.h>
#include <float.h>

// ---------------- problem constants ----------------
#define BB 8
#define SS 128
#define HH 768
#define NS 996           // number of spans per batch (sum_{w=1..8} 129-w)
#define HID 150
#define NZ 64            // int(S * 0.5)
#define NPAIR (NZ*NZ)    // 4096
#define NSPANS_TOT (BB*NS)      // 7968
#define NPAIRS_TOT (BB*NPAIR)   // 32768
#define NCAT 900         // 6 slabs of 150 projected columns

// output regions (floats)
#define OUT_SPANS 0
#define OUT_CAND  (BB*NS*3)                 // 23904
#define OUT_TIDX  (OUT_CAND + BB*NPAIR*4)   // 154976
#define OUT_OIDX  (OUT_TIDX + BB*NZ)        // 155488

// ---------------- scratch (__device__ globals; no allocation) ----------------
__device__ float g_Wcat[HH * NCAT];             // 2.76 MB
__device__ float g_XH[BB * SS * NCAT];          // 3.7 MB   projections of x
__device__ float g_WEs[8 * HID];                // width tables
__device__ float g_WEt[8 * HID];
__device__ float g_WEo[8 * HID];
__device__ float g_Dtab[10 * HID];
__device__ float g_H1s[NSPANS_TOT * HID];       // 4.8 MB
__device__ float g_H2s[NSPANS_TOT * HID];
__device__ float g_probA[BB * 1024];
__device__ float g_probO[BB * 1024];
__device__ int   g_tIdx[BB * NZ];
__device__ int   g_oIdx[BB * NZ];
__device__ int   g_tS[BB * NZ], g_tE[BB * NZ], g_oS[BB * NZ], g_oE[BB * NZ];
__device__ float g_T[BB * NZ * HID];
__device__ float g_O[BB * NZ * HID];
__device__ float g_H1p[NPAIRS_TOT * HID];       // 19.7 MB
__device__ float g_H2p[NPAIRS_TOT * HID];       // 19.7 MB

// span index decode: spans enumerated width w=1..8, starts ascending
__device__ __forceinline__ void span_decode(int i, int& s, int& e, int& w) {
    int off = 0;
#pragma unroll
    for (int wi = 1; wi <= 8; ++wi) {
        int cnt = SS - wi + 1;
        if (i < off + cnt) { s = i - off; e = s + wi - 1; w = wi - 1; return; }
        off += cnt;
    }
    s = 0; e = 0; w = 0;
}

// ---------------- K1: gather concatenated weight matrix Wcat[768,900] ----------------
// slabs (cols): 0:XA(sW1 0..767) 1:XB(sW1 768..1535) 2:XAp(pW1 0..) 3:XBp(pW1 768..)
//               4:XCp(pW1 1556..) 5:XDp(pW1 2324..)
__global__ void build_wcat(const float* __restrict__ sW1, const float* __restrict__ pW1) {
    int idx = blockIdx.x * blockDim.x + threadIdx.x;
    if (idx >= HH * NCAT) return;
    int k = idx / NCAT, col = idx % NCAT;
    int slab = col / HID, c = col % HID;
    float v;
    switch (slab) {
        case 0: v = sW1[(k) * HID + c]; break;
        case 1: v = sW1[(768 + k) * HID + c]; break;
        case 2: v = pW1[(k) * HID + c]; break;
        case 3: v = pW1[(768 + k) * HID + c]; break;
        case 4: v = pW1[(1556 + k) * HID + c]; break;
        default: v = pW1[(2324 + k) * HID + c]; break;
    }
    g_Wcat[idx] = v;
}

// ---------------- K2: tiny tables ----------------
__global__ void tables_kernel(const float* __restrict__ width_emb,
                              const float* __restrict__ sW1, const float* __restrict__ sb1,
                              const float* __restrict__ dist_emb,
                              const float* __restrict__ pW1, const float* __restrict__ pb1) {
    int blk = blockIdx.x;
    int n = threadIdx.x;
    if (n >= HID) return;
    if (blk < 8) {
        float acc = sb1[n];
        for (int k = 0; k < 20; ++k) acc += width_emb[blk * 20 + k] * sW1[(1536 + k) * HID + n];
        g_WEs[blk * HID + n] = acc;
    } else if (blk < 16) {
        int r = blk - 8; float acc = 0.f;
        for (int k = 0; k < 20; ++k) acc += width_emb[r * 20 + k] * pW1[(1536 + k) * HID + n];
        g_WEt[r * HID + n] = acc;
    } else if (blk < 24) {
        int r = blk - 16; float acc = 0.f;
        for (int k = 0; k < 20; ++k) acc += width_emb[r * 20 + k] * pW1[(3092 + k) * HID + n];
        g_WEo[r * HID + n] = acc;
    } else {
        int r = blk - 24; float acc = pb1[n];
        for (int k = 0; k < 128; ++k) acc += dist_emb[r * 128 + k] * pW1[(3112 + k) * HID + n];
        g_Dtab[r * HID + n] = acc;
    }
}

// ---------------- SGEMM: C[M,N] = act(A[M,K] @ W[K,N] + bias) ----------------
// BM=64, BN=150 (one slab), BK=16. blockDim (32,8)=256. Each thread: 8 rows x 5 cols.
__global__ void sgemm150(const float* __restrict__ A, const float* __restrict__ W,
                         const float* __restrict__ bias, float* __restrict__ C,
                         int M, int K, int N, int doRelu) {
    __shared__ float As[64][17];
    __shared__ float Ws[16][152];
    int m0 = blockIdx.x * 64;
    int n0 = blockIdx.y * 150;
    int tx = threadIdx.x, ty = threadIdx.y;
    int tid = ty * 32 + tx;

    float acc[8][5];
#pragma unroll
    for (int r = 0; r < 8; ++r)
#pragma unroll
        for (int t = 0; t < 5; ++t) acc[r][t] = 0.f;

    for (int k0 = 0; k0 < K; k0 += 16) {
        for (int idx = tid; idx < 1024; idx += 256) {
            int r = idx >> 4, kk = idx & 15;
            int gm = m0 + r, gk = k0 + kk;
            As[r][kk] = (gm < M && gk < K) ? A[(size_t)gm * K + gk] : 0.f;
        }
        for (int idx = tid; idx < 2400; idx += 256) {
            int kk = idx / 150, n = idx % 150;
            int gk = k0 + kk;
            Ws[kk][n] = (gk < K) ? W[(size_t)gk * N + n0 + n] : 0.f;
        }
        __syncthreads();
#pragma unroll
        for (int kk = 0; kk < 16; ++kk) {
            float a[8], w[5];
#pragma unroll
            for (int r = 0; r < 8; ++r) a[r] = As[ty + 8 * r][kk];
#pragma unroll
            for (int t = 0; t < 5; ++t) {
                int n = tx + 32 * t;
                w[t] = (n < 150) ? Ws[kk][n] : 0.f;
            }
#pragma unroll
            for (int r = 0; r < 8; ++r)
#pragma unroll
                for (int t = 0; t < 5; ++t) acc[r][t] = fmaf(a[r], w[t], acc[r][t]);
        }
        __syncthreads();
    }
#pragma unroll
    for (int r = 0; r < 8; ++r) {
        int gm = m0 + ty + 8 * r;
        if (gm >= M) continue;
#pragma unroll
        for (int t = 0; t < 5; ++t) {
            int n = tx + 32 * t;
            if (n < 150) {
                float v = acc[r][t];
                if (bias) v += bias[n];
                if (doRelu) v = fmaxf(v, 0.f);
                C[(size_t)gm * N + n0 + n] = v;
            }
        }
    }
}

// ---------------- K4: span h1 = relu(XA[s] + XB[e] + WEs[w]) ----------------
__global__ void span_h1_kernel() {
    int idx = blockIdx.x * blockDim.x + threadIdx.x;
    if (idx >= NSPANS_TOT * HID) return;
    int span = idx / HID, c = idx % HID;
    int b = span / NS, i = span % NS;
    int s, e, w; span_decode(i, s, e, w);
    const float* row_s = g_XH + (size_t)(b * SS + s) * NCAT;
    const float* row_e = g_XH + (size_t)(b * SS + e) * NCAT;
    float v = row_s[c] + row_e[150 + c] + g_WEs[w * HID + c];
    g_H1s[idx] = fmaxf(v, 0.f);
}

// ---------------- K6: span head: logits(3) + softmax; stash class probs ----------------
__global__ void span_head(const float* __restrict__ sW3, const float* __restrict__ sb3,
                          float* __restrict__ outF) {
    int gwarp = (blockIdx.x * blockDim.x + threadIdx.x) >> 5;
    int lane = threadIdx.x & 31;
    if (gwarp >= NSPANS_TOT) return;
    const float* h = g_H2s + (size_t)gwarp * HID;
    float a0 = 0.f, a1 = 0.f, a2 = 0.f;
    for (int k = lane; k < HID; k += 32) {
        float hv = h[k];
        a0 += hv * sW3[k * 3 + 0];
        a1 += hv * sW3[k * 3 + 1];
        a2 += hv * sW3[k * 3 + 2];
    }
#pragma unroll
    for (int off = 16; off; off >>= 1) {
        a0 += __shfl_xor_sync(0xffffffffu, a0, off);
        a1 += __shfl_xor_sync(0xffffffffu, a1, off);
        a2 += __shfl_xor_sync(0xffffffffu, a2, off);
    }
    if (lane == 0) {
        a0 += sb3[0]; a1 += sb3[1]; a2 += sb3[2];
        float m = fmaxf(a0, fmaxf(a1, a2));
        float e0 = expf(a0 - m), e1 = expf(a1 - m), e2 = expf(a2 - m);
        float inv = 1.f / (e0 + e1 + e2);
        float* o = outF + OUT_SPANS + (size_t)gwarp * 3;
        o[0] = e0 * inv; o[1] = e1 * inv; o[2] = e2 * inv;
        int b = gwarp / NS, i = gwarp % NS;
        g_probA[b * 1024 + i] = e1 * inv;
        g_probO[b * 1024 + i] = e2 * inv;
    }
}

// ---------------- K7: top-64 of 996 per (batch, class) via bitonic sort ----------------
// Tie-break matches jax.lax.top_k: descending value, ascending index on ties.
__global__ void topk_kernel(float* __restrict__ outF) {
    __shared__ float v[1024];
    __shared__ int   id[1024];
    int bx = blockIdx.x;
    int b = bx >> 1, cls = bx & 1;
    const float* src = cls ? g_probO : g_probA;
    for (int i = threadIdx.x; i < 1024; i += 256) {
        v[i] = (i < NS) ? src[b * 1024 + i] : -FLT_MAX;
        id[i] = i;
    }
    __syncthreads();
    for (int k = 2; k <= 1024; k <<= 1) {
        for (int j = k >> 1; j > 0; j >>= 1) {
            for (int i = threadIdx.x; i < 1024; i += 256) {
                int ixj = i ^ j;
                if (ixj > i) {
                    float va = v[i], vb = v[ixj];
                    int ia = id[i], ib = id[ixj];
                    bool bBefore = (vb > va) || (vb == va && ib < ia);
                    bool dirUp = ((i & k) == 0);
                    if (bBefore == dirUp) {
                        v[i] = vb; v[ixj] = va;
                        id[i] = ib; id[ixj] = ia;
                    }
                }
            }
            __syncthreads();
        }
    }
    if (threadIdx.x < NZ) {
        int idx = id[threadIdx.x];
        if (cls == 0) {
            g_tIdx[b * NZ + threadIdx.x] = idx;
            outF[OUT_TIDX + b * NZ + threadIdx.x] = (float)idx;
        } else {
            g_oIdx[b * NZ + threadIdx.x] = idx;
            outF[OUT_OIDX + b * NZ + threadIdx.x] = (float)idx;
        }
    }
}

// ---------------- K8: per-(b,i) target/opinion projected rows + start/end ----------------
__global__ void pair_tables() {
    int blk = blockIdx.x;            // 0..1023
    int which = blk >> 9;            // 0 target, 1 opinion
    int bi = blk & 511;
    int b = bi >> 6;
    int span = which ? g_oIdx[bi] : g_tIdx[bi];
    int s, e, w; span_decode(span, s, e, w);
    int c = threadIdx.x;
    const float* row_s = g_XH + (size_t)(b * SS + s) * NCAT;
    const float* row_e = g_XH + (size_t)(b * SS + e) * NCAT;
    if (c < HID) {
        if (!which)
            g_T[bi * HID + c] = row_s[300 + c] + row_e[450 + c] + g_WEt[w * HID + c];
        else
            g_O[bi * HID + c] = row_s[600 + c] + row_e[750 + c] + g_WEo[w * HID + c];
    }
    if (c == 0) {
        if (!which) { g_tS[bi] = s; g_tE[bi] = e; }
        else        { g_oS[bi] = s; g_oE[bi] = e; }
    }
}

// ---------------- K9: pair h1 = relu(T[i] + O[j] + Dtab[bucket]) ----------------
__global__ void pair_h1_kernel() {
    int p = blockIdx.x;              // 0..32767
    int b = p >> 12;
    int ij = p & 4095;
    int i = ij >> 6, j = ij & 63;
    int bi = b * NZ + i, bj = b * NZ + j;
    int dist = min(abs(g_tE[bi] - g_oS[bj]), abs(g_tS[bi] - g_oE[bj]));
    int bucket = dist >= 64 ? 9 : dist >= 32 ? 8 : dist >= 16 ? 7 : dist >= 8 ? 6 : dist >= 5 ? 5 : dist;
    int c = threadIdx.x;
    if (c < HID) {
        float v = g_T[bi * HID + c] + g_O[bj * HID + c] + g_Dtab[bucket * HID + c];
        g_H1p[(size_t)p * HID + c] = fmaxf(v, 0.f);
    }
}

// ---------------- K11: pair head: logits(4) + softmax ----------------
__global__ void pair_head(const float* __restrict__ pW3, const float* __restrict__ pb3,
                          float* __restrict__ outF) {
    int gwarp = (blockIdx.x * blockDim.x + threadIdx.x) >> 5;
    int lane = threadIdx.x & 31;
    if (gwarp >= NPAIRS_TOT) return;
    const float* h = g_H2p + (size_t)gwarp * HID;
    float a0 = 0.f, a1 = 0.f, a2 = 0.f, a3 = 0.f;
    for (int k = lane; k < HID; k += 32) {
        float hv = h[k];
        a0 += hv * pW3[k * 4 + 0];
        a1 += hv * pW3[k * 4 + 1];
        a2 += hv * pW3[k * 4 + 2];
        a3 += hv * pW3[k * 4 + 3];
    }
#pragma unroll
    for (int off = 16; off; off >>= 1) {
        a0 += __shfl_xor_sync(0xffffffffu, a0, off);
        a1 += __shfl_xor_sync(0xffffffffu, a1, off);
        a2 += __shfl_xor_sync(0xffffffffu, a2, off);
        a3 += __shfl_xor_sync(0xffffffffu, a3, off);
    }
    if (lane == 0) {
        a0 += pb3[0]; a1 += pb3[1]; a2 += pb3[2]; a3 += pb3[3];
        float m = fmaxf(fmaxf(a0, a1), fmaxf(a2, a3));
        float e0 = expf(a0 - m), e1 = expf(a1 - m), e2 = expf(a2 - m), e3 = expf(a3 - m);
        float inv = 1.f / (e0 + e1 + e2 + e3);
        float* o = outF + OUT_CAND + (size_t)gwarp * 4;
        o[0] = e0 * inv; o[1] = e1 * inv; o[2] = e2 * inv; o[3] = e3 * inv;
    }
}

// ---------------- launch ----------------
extern "C" void kernel_launch(void* const* d_in, const int* in_sizes, int n_in,
                              void* d_out, int out_size) {
    const float* x        = (const float*)d_in[0];
    const float* width_e  = (const float*)d_in[1];
    const float* sW1      = (const float*)d_in[2];
    const float* sb1      = (const float*)d_in[3];
    const float* sW2      = (const float*)d_in[4];
    const float* sb2      = (const float*)d_in[5];
    const float* sW3      = (const float*)d_in[6];
    const float* sb3      = (const float*)d_in[7];
    const float* dist_e   = (const float*)d_in[8];
    const float* pW1      = (const float*)d_in[9];
    const float* pb1      = (const float*)d_in[10];
    const float* pW2      = (const float*)d_in[11];
    const float* pb2      = (const float*)d_in[12];
    const float* pW3      = (const float*)d_in[13];
    const float* pb3      = (const float*)d_in[14];
    float* outF = (float*)d_out;

    float *Wcat, *XH, *H1s, *H2s, *H1p, *H2p;
    cudaGetSymbolAddress((void**)&Wcat, g_Wcat);
    cudaGetSymbolAddress((void**)&XH,   g_XH);
    cudaGetSymbolAddress((void**)&H1s,  g_H1s);
    cudaGetSymbolAddress((void**)&H2s,  g_H2s);
    cudaGetSymbolAddress((void**)&H1p,  g_H1p);
    cudaGetSymbolAddress((void**)&H2p,  g_H2p);

    // K1: Wcat gather
    build_wcat<<<(HH * NCAT + 255) / 256, 256>>>(sW1, pW1);
    // K2: small tables
    tables_kernel<<<34, 160>>>(width_e, sW1, sb1, dist_e, pW1, pb1);
    // K3: XH = x @ Wcat   [1024 x 900]
    {
        dim3 grid((BB * SS + 63) / 64, NCAT / 150), blk(32, 8);
        sgemm150<<<grid, blk>>>(x, Wcat, nullptr, XH, BB * SS, HH, NCAT, 0);
    }
    // K4: span h1
    span_h1_kernel<<<(NSPANS_TOT * HID + 255) / 256, 256>>>();
    // K5: span h2 = relu(h1 @ sW2 + sb2)
    {
        dim3 grid((NSPANS_TOT + 63) / 64, 1), blk(32, 8);
        sgemm150<<<grid, blk>>>(H1s, sW2, sb2, H2s, NSPANS_TOT, HID, HID, 1);
    }
    // K6: span logits/softmax
    span_head<<<(NSPANS_TOT * 32 + 255) / 256, 256>>>(sW3, sb3, outF);
    // K7: topk per (batch, class)
    topk_kernel<<<BB * 2, 256>>>(outF);
    // K8: gather projected target/opinion rows
    pair_tables<<<2 * BB * NZ, 160>>>();
    // K9: pair h1
    pair_h1_kernel<<<NPAIRS_TOT, 160>>>();
    // K10: pair h2 = relu(h1 @ pW2 + pb2)
    {
        dim3 grid((NPAIRS_TOT + 63) / 64, 1), blk(32, 8);
        sgemm150<<<grid, blk>>>(H1p, pW2, pb2, H2p, NPAIRS_TOT, HID, HID, 1);
    }
    // K11: pair logits/softmax
    pair_head<<<(NPAIRS_TOT * 32 + 255) / 256, 256>>>(pW3, pb3, outF);
}

// round 3
// speedup vs baseline: 1.3647x; 1.3647x over previous
#include <cuda_runtime.h>
#include <math.h>
#include <float.h>

// ---------------- problem constants ----------------
#define BB 8
#define SS 128
#define HH 768
#define NS 996           // spans per batch
#define HID 150
#define NZ 64
#define NPAIR (NZ*NZ)
#define NSPANS_TOT (BB*NS)      // 7968
#define NPAIRS_TOT (BB*NPAIR)   // 32768
#define NCAT 900

// output regions (floats)
#define OUT_SPANS 0
#define OUT_CAND  (BB*NS*3)                 // 23904
#define OUT_TIDX  (OUT_CAND + BB*NPAIR*4)   // 154976
#define OUT_OIDX  (OUT_TIDX + BB*NZ)        // 155488

// ---------------- scratch ----------------
__device__ float g_Wcat[HH * NCAT];
__device__ float g_XH[BB * SS * NCAT];
__device__ float g_WEs[8 * HID];
__device__ float g_WEt[8 * HID];
__device__ float g_WEo[8 * HID];
__device__ float g_Dtab[10 * HID];
__device__ float g_probA[BB * 1024];
__device__ float g_probO[BB * 1024];
__device__ int   g_tIdx[BB * NZ];
__device__ int   g_oIdx[BB * NZ];
__device__ int   g_tS[BB * NZ], g_tE[BB * NZ], g_oS[BB * NZ], g_oE[BB * NZ];
__device__ float g_T[BB * NZ * HID];
__device__ float g_O[BB * NZ * HID];

// ---------------- packed fp32x2 FMA (Blackwell) ----------------
union F2U { float2 f; unsigned long long u; };
static __device__ __forceinline__ float2 ffma2(float2 a, float2 b, float2 c) {
    F2U A, B, C, D; A.f = a; B.f = b; C.f = c;
    asm("fma.rn.f32x2 %0, %1, %2, %3;" : "=l"(D.u) : "l"(A.u), "l"(B.u), "l"(C.u));
    return D.f;
}

__device__ __forceinline__ void span_decode(int i, int& s, int& e, int& w) {
    int off = 0;
#pragma unroll
    for (int wi = 1; wi <= 8; ++wi) {
        int cnt = SS - wi + 1;
        if (i < off + cnt) { s = i - off; e = s + wi - 1; w = wi - 1; return; }
        off += cnt;
    }
    s = 0; e = 0; w = 0;
}

// ---------------- K1: Wcat gather ----------------
__global__ void build_wcat(const float* __restrict__ sW1, const float* __restrict__ pW1) {
    int idx = blockIdx.x * blockDim.x + threadIdx.x;
    if (idx >= HH * NCAT) return;
    int k = idx / NCAT, col = idx % NCAT;
    int slab = col / HID, c = col % HID;
    float v;
    switch (slab) {
        case 0: v = sW1[(k) * HID + c]; break;
        case 1: v = sW1[(768 + k) * HID + c]; break;
        case 2: v = pW1[(k) * HID + c]; break;
        case 3: v = pW1[(768 + k) * HID + c]; break;
        case 4: v = pW1[(1556 + k) * HID + c]; break;
        default: v = pW1[(2324 + k) * HID + c]; break;
    }
    g_Wcat[idx] = v;
}

// ---------------- K2: tiny tables ----------------
__global__ void tables_kernel(const float* __restrict__ width_emb,
                              const float* __restrict__ sW1, const float* __restrict__ sb1,
                              const float* __restrict__ dist_emb,
                              const float* __restrict__ pW1, const float* __restrict__ pb1) {
    int blk = blockIdx.x;
    int n = threadIdx.x;
    if (n >= HID) return;
    if (blk < 8) {
        float acc = sb1[n];
        for (int k = 0; k < 20; ++k) acc += width_emb[blk * 20 + k] * sW1[(1536 + k) * HID + n];
        g_WEs[blk * HID + n] = acc;
    } else if (blk < 16) {
        int r = blk - 8; float acc = 0.f;
        for (int k = 0; k < 20; ++k) acc += width_emb[r * 20 + k] * pW1[(1536 + k) * HID + n];
        g_WEt[r * HID + n] = acc;
    } else if (blk < 24) {
        int r = blk - 16; float acc = 0.f;
        for (int k = 0; k < 20; ++k) acc += width_emb[r * 20 + k] * pW1[(3092 + k) * HID + n];
        g_WEo[r * HID + n] = acc;
    } else {
        int r = blk - 24; float acc = pb1[n];
        for (int k = 0; k < 128; ++k) acc += dist_emb[r * 128 + k] * pW1[(3112 + k) * HID + n];
        g_Dtab[r * HID + n] = acc;
    }
}

// ---------------- K3: XH = x @ Wcat   [1024 x 900], f32x2 inner loop ----------------
__global__ void proj_gemm(const float* __restrict__ A) {
    __shared__ __align__(16) float As[64][17];
    __shared__ __align__(16) float Ws[16][152];
    int m0 = blockIdx.x * 64, n0 = blockIdx.y * 150;
    int tx = threadIdx.x, ty = threadIdx.y, tid = ty * 32 + tx;
    const float2 z2 = make_float2(0.f, 0.f);
    float2 acc[8][3];
#pragma unroll
    for (int r = 0; r < 8; ++r)
#pragma unroll
        for (int t = 0; t < 3; ++t) acc[r][t] = z2;

    for (int k0 = 0; k0 < HH; k0 += 16) {
        for (int idx = tid; idx < 1024; idx += 256) {
            int r = idx >> 4, kk = idx & 15;
            As[r][kk] = A[(size_t)(m0 + r) * HH + k0 + kk];
        }
        for (int idx = tid; idx < 2432; idx += 256) {
            int kk = idx / 152, c = idx % 152;
            Ws[kk][c] = (c < 150) ? g_Wcat[(size_t)(k0 + kk) * NCAT + n0 + c] : 0.f;
        }
        __syncthreads();
#pragma unroll
        for (int kk = 0; kk < 16; ++kk) {
            const float2* wp = reinterpret_cast<const float2*>(&Ws[kk][0]);
            float2 w0 = wp[tx], w1 = wp[tx + 32];
            float2 w2 = (tx < 11) ? wp[tx + 64] : z2;   // pairs 64..74 only (cols 128..149)
            float a[8];
#pragma unroll
            for (int r = 0; r < 8; ++r) a[r] = As[ty + 8 * r][kk];
#pragma unroll
            for (int r = 0; r < 8; ++r) {
                float2 ad = make_float2(a[r], a[r]);
                acc[r][0] = ffma2(ad, w0, acc[r][0]);
                acc[r][1] = ffma2(ad, w1, acc[r][1]);
                acc[r][2] = ffma2(ad, w2, acc[r][2]);
            }
        }
        __syncthreads();
    }
#pragma unroll
    for (int r = 0; r < 8; ++r) {
        int gm = m0 + ty + 8 * r;
        float2* orow = reinterpret_cast<float2*>(g_XH + (size_t)gm * NCAT + n0);
        orow[tx] = acc[r][0];
        orow[tx + 32] = acc[r][1];
        if (tx < 11) orow[tx + 64] = acc[r][2];
    }
}

// ---------------- K4: fused span pipeline (h1 -> h2 -> head -> softmax) ----------------
__global__ void span_fused(const float* __restrict__ sW2, const float* __restrict__ sb2,
                           const float* __restrict__ sW3, const float* __restrict__ sb3,
                           float* __restrict__ outF) {
    __shared__ __align__(16) float As[64][17];
    __shared__ __align__(16) float Ws[16][152];
    __shared__ int rowS[64], rowE[64], wOff[64];
    __shared__ float b2s[152];
    __shared__ float W3s[456];
    int m0 = blockIdx.x * 64;
    int tx = threadIdx.x, ty = threadIdx.y, tid = ty * 32 + tx;
    const float2 z2 = make_float2(0.f, 0.f);

    if (tid < 64) {
        int gm = m0 + tid;
        if (gm < NSPANS_TOT) {
            int b = gm / NS, i = gm % NS, s, e, w;
            span_decode(i, s, e, w);
            rowS[tid] = (b * SS + s) * NCAT;
            rowE[tid] = (b * SS + e) * NCAT + 150;
            wOff[tid] = w * HID;
        } else { rowS[tid] = -1; rowE[tid] = 0; wOff[tid] = 0; }
    }
    for (int c = tid; c < 150; c += 256) b2s[c] = sb2[c];
    for (int c = tid; c < 450; c += 256) W3s[c] = sW3[c];
    if (tid < 3) W3s[450 + tid] = sb3[tid];
    __syncthreads();

    float2 acc[8][3];
#pragma unroll
    for (int r = 0; r < 8; ++r)
#pragma unroll
        for (int t = 0; t < 3; ++t) acc[r][t] = z2;

    for (int k0 = 0; k0 < HID; k0 += 16) {
        for (int idx = tid; idx < 1024; idx += 256) {
            int r = idx >> 4, kk = idx & 15, gk = k0 + kk;
            float v = 0.f;
            if (rowS[r] >= 0 && gk < HID)
                v = fmaxf(g_XH[rowS[r] + gk] + g_XH[rowE[r] + gk] + g_WEs[wOff[r] + gk], 0.f);
            As[r][kk] = v;
        }
        for (int idx = tid; idx < 2432; idx += 256) {
            int kk = idx / 152, c = idx % 152, gk = k0 + kk;
            Ws[kk][c] = (c < 150 && gk < HID) ? sW2[(size_t)gk * HID + c] : 0.f;
        }
        __syncthreads();
#pragma unroll
        for (int kk = 0; kk < 16; ++kk) {
            const float2* wp = reinterpret_cast<const float2*>(&Ws[kk][0]);
            float2 w0 = wp[tx], w1 = wp[tx + 32];
            float2 w2 = (tx < 11) ? wp[tx + 64] : z2;
            float a[8];
#pragma unroll
            for (int r = 0; r < 8; ++r) a[r] = As[ty + 8 * r][kk];
#pragma unroll
            for (int r = 0; r < 8; ++r) {
                float2 ad = make_float2(a[r], a[r]);
                acc[r][0] = ffma2(ad, w0, acc[r][0]);
                acc[r][1] = ffma2(ad, w1, acc[r][1]);
                acc[r][2] = ffma2(ad, w2, acc[r][2]);
            }
        }
        __syncthreads();
    }

#pragma unroll
    for (int rr = 0; rr < 8; ++rr) {
        int gm = m0 + ty + 8 * rr;
        float p0 = 0.f, p1 = 0.f, p2 = 0.f;
#pragma unroll
        for (int t = 0; t < 3; ++t) {
            int c0 = 2 * tx + 64 * t, c1 = c0 + 1;
            if (c0 < 150) {
                float v = fmaxf(acc[rr][t].x + b2s[c0], 0.f);
                p0 += v * W3s[c0 * 3 + 0]; p1 += v * W3s[c0 * 3 + 1]; p2 += v * W3s[c0 * 3 + 2];
            }
            if (c1 < 150) {
                float v = fmaxf(acc[rr][t].y + b2s[c1], 0.f);
                p0 += v * W3s[c1 * 3 + 0]; p1 += v * W3s[c1 * 3 + 1]; p2 += v * W3s[c1 * 3 + 2];
            }
        }
#pragma unroll
        for (int off = 16; off; off >>= 1) {
            p0 += __shfl_xor_sync(0xffffffffu, p0, off);
            p1 += __shfl_xor_sync(0xffffffffu, p1, off);
            p2 += __shfl_xor_sync(0xffffffffu, p2, off);
        }
        if (tx == 0 && gm < NSPANS_TOT) {
            float a0 = p0 + W3s[450], a1 = p1 + W3s[451], a2 = p2 + W3s[452];
            float m = fmaxf(a0, fmaxf(a1, a2));
            float e0 = expf(a0 - m), e1 = expf(a1 - m), e2 = expf(a2 - m);
            float inv = 1.f / (e0 + e1 + e2);
            float* o = outF + OUT_SPANS + (size_t)gm * 3;
            o[0] = e0 * inv; o[1] = e1 * inv; o[2] = e2 * inv;
            int b = gm / NS, i = gm % NS;
            g_probA[b * 1024 + i] = e1 * inv;
            g_probO[b * 1024 + i] = e2 * inv;
        }
    }
}

// ---------------- K5: top-64 per (batch, class) ----------------
__global__ void topk_kernel(float* __restrict__ outF) {
    __shared__ float v[1024];
    __shared__ int   id[1024];
    int bx = blockIdx.x;
    int b = bx >> 1, cls = bx & 1;
    const float* src = cls ? g_probO : g_probA;
    for (int i = threadIdx.x; i < 1024; i += 256) {
        v[i] = (i < NS) ? src[b * 1024 + i] : -FLT_MAX;
        id[i] = i;
    }
    __syncthreads();
    for (int k = 2; k <= 1024; k <<= 1) {
        for (int j = k >> 1; j > 0; j >>= 1) {
            for (int i = threadIdx.x; i < 1024; i += 256) {
                int ixj = i ^ j;
                if (ixj > i) {
                    float va = v[i], vb = v[ixj];
                    int ia = id[i], ib = id[ixj];
                    bool bBefore = (vb > va) || (vb == va && ib < ia);
                    bool dirUp = ((i & k) == 0);
                    if (bBefore == dirUp) {
                        v[i] = vb; v[ixj] = va;
                        id[i] = ib; id[ixj] = ia;
                    }
                }
            }
            __syncthreads();
        }
    }
    if (threadIdx.x < NZ) {
        int idx = id[threadIdx.x];
        if (cls == 0) {
            g_tIdx[b * NZ + threadIdx.x] = idx;
            outF[OUT_TIDX + b * NZ + threadIdx.x] = (float)idx;
        } else {
            g_oIdx[b * NZ + threadIdx.x] = idx;
            outF[OUT_OIDX + b * NZ + threadIdx.x] = (float)idx;
        }
    }
}

// ---------------- K6: per-(b,i) target/opinion projected rows ----------------
__global__ void pair_tables() {
    int blk = blockIdx.x;
    int which = blk >> 9;
    int bi = blk & 511;
    int b = bi >> 6;
    int span = which ? g_oIdx[bi] : g_tIdx[bi];
    int s, e, w; span_decode(span, s, e, w);
    int c = threadIdx.x;
    const float* row_s = g_XH + (size_t)(b * SS + s) * NCAT;
    const float* row_e = g_XH + (size_t)(b * SS + e) * NCAT;
    if (c < HID) {
        if (!which)
            g_T[bi * HID + c] = row_s[300 + c] + row_e[450 + c] + g_WEt[w * HID + c];
        else
            g_O[bi * HID + c] = row_s[600 + c] + row_e[750 + c] + g_WEo[w * HID + c];
    }
    if (c == 0) {
        if (!which) { g_tS[bi] = s; g_tE[bi] = e; }
        else        { g_oS[bi] = s; g_oE[bi] = e; }
    }
}

// ---------------- K7: fused pair pipeline ----------------
__global__ void pair_fused(const float* __restrict__ pW2, const float* __restrict__ pb2,
                           const float* __restrict__ pW3, const float* __restrict__ pb3,
                           float* __restrict__ outF) {
    __shared__ __align__(16) float As[64][17];
    __shared__ __align__(16) float Ws[16][152];
    __shared__ float Trow[152];
    __shared__ int oBase[64], dOff[64];
    __shared__ float b2s[152];
    __shared__ float W3s[608];
    int p0 = blockIdx.x * 64;         // 64 pairs: fixed (b,i), all j
    int b = p0 >> 12;
    int i = (p0 >> 6) & 63;
    int bi = b * NZ + i;
    int tx = threadIdx.x, ty = threadIdx.y, tid = ty * 32 + tx;
    const float2 z2 = make_float2(0.f, 0.f);

    if (tid < 64) {
        int j = tid, bj = b * NZ + j;
        oBase[j] = bj * HID;
        int dist = min(abs(g_tE[bi] - g_oS[bj]), abs(g_tS[bi] - g_oE[bj]));
        int bucket = dist >= 64 ? 9 : dist >= 32 ? 8 : dist >= 16 ? 7 : dist >= 8 ? 6 : dist >= 5 ? 5 : dist;
        dOff[j] = bucket * HID;
    }
    if (tid < 150) Trow[tid] = g_T[bi * HID + tid];
    for (int c = tid; c < 150; c += 256) b2s[c] = pb2[c];
    for (int c = tid; c < 600; c += 256) W3s[c] = pW3[c];
    if (tid < 4) W3s[600 + tid] = pb3[tid];
    __syncthreads();

    float2 acc[8][3];
#pragma unroll
    for (int r = 0; r < 8; ++r)
#pragma unroll
        for (int t = 0; t < 3; ++t) acc[r][t] = z2;

    for (int k0 = 0; k0 < HID; k0 += 16) {
        for (int idx = tid; idx < 1024; idx += 256) {
            int r = idx >> 4, kk = idx & 15, gk = k0 + kk;
            float v = 0.f;
            if (gk < HID)
                v = fmaxf(Trow[gk] + g_O[oBase[r] + gk] + g_Dtab[dOff[r] + gk], 0.f);
            As[r][kk] = v;
        }
        for (int idx = tid; idx < 2432; idx += 256) {
            int kk = idx / 152, c = idx % 152, gk = k0 + kk;
            Ws[kk][c] = (c < 150 && gk < HID) ? pW2[(size_t)gk * HID + c] : 0.f;
        }
        __syncthreads();
#pragma unroll
        for (int kk = 0; kk < 16; ++kk) {
            const float2* wp = reinterpret_cast<const float2*>(&Ws[kk][0]);
            float2 w0 = wp[tx], w1 = wp[tx + 32];
            float2 w2 = (tx < 11) ? wp[tx + 64] : z2;
            float a[8];
#pragma unroll
            for (int r = 0; r < 8; ++r) a[r] = As[ty + 8 * r][kk];
#pragma unroll
            for (int r = 0; r < 8; ++r) {
                float2 ad = make_float2(a[r], a[r]);
                acc[r][0] = ffma2(ad, w0, acc[r][0]);
                acc[r][1] = ffma2(ad, w1, acc[r][1]);
                acc[r][2] = ffma2(ad, w2, acc[r][2]);
            }
        }
        __syncthreads();
    }

#pragma unroll
    for (int rr = 0; rr < 8; ++rr) {
        int gm = p0 + ty + 8 * rr;
        float q0 = 0.f, q1 = 0.f, q2 = 0.f, q3 = 0.f;
#pragma unroll
        for (int t = 0; t < 3; ++t) {
            int c0 = 2 * tx + 64 * t, c1 = c0 + 1;
            if (c0 < 150) {
                float v = fmaxf(acc[rr][t].x + b2s[c0], 0.f);
                q0 += v * W3s[c0 * 4 + 0]; q1 += v * W3s[c0 * 4 + 1];
                q2 += v * W3s[c0 * 4 + 2]; q3 += v * W3s[c0 * 4 + 3];
            }
            if (c1 < 150) {
                float v = fmaxf(acc[rr][t].y + b2s[c1], 0.f);
                q0 += v * W3s[c1 * 4 + 0]; q1 += v * W3s[c1 * 4 + 1];
                q2 += v * W3s[c1 * 4 + 2]; q3 += v * W3s[c1 * 4 + 3];
            }
        }
#pragma unroll
        for (int off = 16; off; off >>= 1) {
            q0 += __shfl_xor_sync(0xffffffffu, q0, off);
            q1 += __shfl_xor_sync(0xffffffffu, q1, off);
            q2 += __shfl_xor_sync(0xffffffffu, q2, off);
            q3 += __shfl_xor_sync(0xffffffffu, q3, off);
        }
        if (tx == 0) {
            float a0 = q0 + W3s[600], a1 = q1 + W3s[601], a2 = q2 + W3s[602], a3 = q3 + W3s[603];
            float m = fmaxf(fmaxf(a0, a1), fmaxf(a2, a3));
            float e0 = expf(a0 - m), e1 = expf(a1 - m), e2 = expf(a2 - m), e3 = expf(a3 - m);
            float inv = 1.f / (e0 + e1 + e2 + e3);
            float* o = outF + OUT_CAND + (size_t)gm * 4;
            o[0] = e0 * inv; o[1] = e1 * inv; o[2] = e2 * inv; o[3] = e3 * inv;
        }
    }
}

// ---------------- launch ----------------
extern "C" void kernel_launch(void* const* d_in, const int* in_sizes, int n_in,
                              void* d_out, int out_size) {
    const float* x        = (const float*)d_in[0];
    const float* width_e  = (const float*)d_in[1];
    const float* sW1      = (const float*)d_in[2];
    const float* sb1      = (const float*)d_in[3];
    const float* sW2      = (const float*)d_in[4];
    const float* sb2      = (const float*)d_in[5];
    const float* sW3      = (const float*)d_in[6];
    const float* sb3      = (const float*)d_in[7];
    const float* dist_e   = (const float*)d_in[8];
    const float* pW1      = (const float*)d_in[9];
    const float* pb1      = (const float*)d_in[10];
    const float* pW2      = (const float*)d_in[11];
    const float* pb2      = (const float*)d_in[12];
    const float* pW3      = (const float*)d_in[13];
    const float* pb3      = (const float*)d_in[14];
    float* outF = (float*)d_out;

    dim3 blk(32, 8);

    build_wcat<<<(HH * NCAT + 255) / 256, 256>>>(sW1, pW1);
    tables_kernel<<<34, 160>>>(width_e, sW1, sb1, dist_e, pW1, pb1);
    proj_gemm<<<dim3(16, 6), blk>>>(x);
    span_fused<<<(NSPANS_TOT + 63) / 64, blk>>>(sW2, sb2, sW3, sb3, outF);
    topk_kernel<<<BB * 2, 256>>>(outF);
    pair_tables<<<2 * BB * NZ, 160>>>();
    pair_fused<<<NPAIRS_TOT / 64, blk>>>(pW2, pb2, pW3, pb3, outF);
}

// round 4
// speedup vs baseline: 1.7089x; 1.2522x over previous
#include <cuda_runtime.h>
#include <math.h>
#include <float.h>

// ---------------- problem constants ----------------
#define BB 8
#define SS 128
#define HH 768
#define NS 996
#define HID 150
#define NZ 64
#define NPAIR (NZ*NZ)
#define NSPANS_TOT (BB*NS)      // 7968 = 249*32
#define NPAIRS_TOT (BB*NPAIR)   // 32768 = 1024*32
#define NCAT 900
#define BM 32

// output regions (floats)
#define OUT_SPANS 0
#define OUT_CAND  (BB*NS*3)                 // 23904
#define OUT_TIDX  (OUT_CAND + BB*NPAIR*4)   // 154976
#define OUT_OIDX  (OUT_TIDX + BB*NZ)        // 155488

// ---------------- scratch ----------------
__device__ float g_XH[BB * SS * NCAT];
__device__ float g_WEs[8 * HID];
__device__ float g_WEt[8 * HID];
__device__ float g_WEo[8 * HID];
__device__ float g_Dtab[10 * HID];
__device__ float g_probA[BB * 1024];
__device__ float g_probO[BB * 1024];
__device__ int   g_tIdx[BB * NZ];
__device__ int   g_oIdx[BB * NZ];
__device__ int   g_tS[BB * NZ], g_tE[BB * NZ], g_oS[BB * NZ], g_oE[BB * NZ];
__device__ float g_T[BB * NZ * HID];
__device__ float g_O[BB * NZ * HID];

// ---------------- packed fp32x2 FMA (Blackwell) ----------------
union F2U { float2 f; unsigned long long u; };
static __device__ __forceinline__ float2 ffma2(float2 a, float2 b, float2 c) {
    F2U A, B, C, D; A.f = a; B.f = b; C.f = c;
    asm("fma.rn.f32x2 %0, %1, %2, %3;" : "=l"(D.u) : "l"(A.u), "l"(B.u), "l"(C.u));
    return D.f;
}

__device__ __forceinline__ void span_decode(int i, int& s, int& e, int& w) {
    int off = 0;
#pragma unroll
    for (int wi = 1; wi <= 8; ++wi) {
        int cnt = SS - wi + 1;
        if (i < off + cnt) { s = i - off; e = s + wi - 1; w = wi - 1; return; }
        off += cnt;
    }
    s = 0; e = 0; w = 0;
}

// ---------------- K2: tiny tables ----------------
__global__ void tables_kernel(const float* __restrict__ width_emb,
                              const float* __restrict__ sW1, const float* __restrict__ sb1,
                              const float* __restrict__ dist_emb,
                              const float* __restrict__ pW1, const float* __restrict__ pb1) {
    int blk = blockIdx.x;
    int n = threadIdx.x;
    if (n >= HID) return;
    if (blk < 8) {
        float acc = sb1[n];
        for (int k = 0; k < 20; ++k) acc += width_emb[blk * 20 + k] * sW1[(1536 + k) * HID + n];
        g_WEs[blk * HID + n] = acc;
    } else if (blk < 16) {
        int r = blk - 8; float acc = 0.f;
        for (int k = 0; k < 20; ++k) acc += width_emb[r * 20 + k] * pW1[(1536 + k) * HID + n];
        g_WEt[r * HID + n] = acc;
    } else if (blk < 24) {
        int r = blk - 16; float acc = 0.f;
        for (int k = 0; k < 20; ++k) acc += width_emb[r * 20 + k] * pW1[(3092 + k) * HID + n];
        g_WEo[r * HID + n] = acc;
    } else {
        int r = blk - 24; float acc = pb1[n];
        for (int k = 0; k < 128; ++k) acc += dist_emb[r * 128 + k] * pW1[(3112 + k) * HID + n];
        g_Dtab[r * HID + n] = acc;
    }
}

// ---------------- K3: XH = x @ slab-weights, double-buffered ----------------
// blockIdx.y selects one of 6 slabs (150 cols each), read directly from sW1/pW1.
__global__ void proj_gemm(const float* __restrict__ A,
                          const float* __restrict__ sW1, const float* __restrict__ pW1) {
    __shared__ __align__(16) float As[2][BM][17];
    __shared__ __align__(16) float Ws[2][16][152];
    int m0 = blockIdx.x * BM;
    int slab = blockIdx.y;
    const float* src;
    switch (slab) {
        case 0: src = sW1; break;
        case 1: src = sW1 + 768 * HID; break;
        case 2: src = pW1; break;
        case 3: src = pW1 + 768 * HID; break;
        case 4: src = pW1 + 1556 * HID; break;
        default: src = pW1 + 2324 * HID; break;
    }
    int tx = threadIdx.x, ty = threadIdx.y, tid = ty * 32 + tx;
    const float2 z2 = make_float2(0.f, 0.f);
    float2 acc[4][3];
#pragma unroll
    for (int r = 0; r < 4; ++r)
#pragma unroll
        for (int t = 0; t < 3; ++t) acc[r][t] = z2;

    // preload tile 0
    {
        int idx = tid;                    // 512 A elems: 2/thread
#pragma unroll
        for (int i = 0; i < 2; ++i, idx += 256)
            As[0][idx >> 4][idx & 15] = A[(size_t)(m0 + (idx >> 4)) * HH + (idx & 15)];
        idx = tid;
#pragma unroll
        for (int i = 0; i < 10; ++i, idx += 256)
            if (idx < 2432) {
                int kk = idx / 152, c = idx % 152;
                Ws[0][kk][c] = (c < 150) ? src[(size_t)kk * HID + c] : 0.f;
            }
    }
    __syncthreads();

    const int NT = HH / 16;   // 48
    for (int t = 0; t < NT; ++t) {
        int buf = t & 1;
        float ar[2]; float wr[10];
        bool hasNext = (t + 1) < NT;
        if (hasNext) {
            int k0 = (t + 1) * 16;
            int idx = tid;
#pragma unroll
            for (int i = 0; i < 2; ++i, idx += 256)
                ar[i] = A[(size_t)(m0 + (idx >> 4)) * HH + k0 + (idx & 15)];
            idx = tid;
#pragma unroll
            for (int i = 0; i < 10; ++i, idx += 256)
                if (idx < 2432) {
                    int kk = idx / 152, c = idx % 152;
                    wr[i] = (c < 150) ? src[(size_t)(k0 + kk) * HID + c] : 0.f;
                }
        }
#pragma unroll
        for (int kk = 0; kk < 16; ++kk) {
            const float2* wp = reinterpret_cast<const float2*>(&Ws[buf][kk][0]);
            float2 w0 = wp[tx], w1 = wp[tx + 32];
            float2 w2 = (tx < 11) ? wp[tx + 64] : z2;
            float a[4];
#pragma unroll
            for (int r = 0; r < 4; ++r) a[r] = As[buf][ty + 8 * r][kk];
#pragma unroll
            for (int r = 0; r < 4; ++r) {
                float2 ad = make_float2(a[r], a[r]);
                acc[r][0] = ffma2(ad, w0, acc[r][0]);
                acc[r][1] = ffma2(ad, w1, acc[r][1]);
                acc[r][2] = ffma2(ad, w2, acc[r][2]);
            }
        }
        if (hasNext) {
            int nb = buf ^ 1;
            int idx = tid;
#pragma unroll
            for (int i = 0; i < 2; ++i, idx += 256)
                As[nb][idx >> 4][idx & 15] = ar[i];
            idx = tid;
#pragma unroll
            for (int i = 0; i < 10; ++i, idx += 256)
                if (idx < 2432) Ws[nb][idx / 152][idx % 152] = wr[i];
        }
        __syncthreads();
    }
#pragma unroll
    for (int r = 0; r < 4; ++r) {
        int gm = m0 + ty + 8 * r;
        float2* orow = reinterpret_cast<float2*>(g_XH + (size_t)gm * NCAT + slab * HID);
        orow[tx] = acc[r][0];
        orow[tx + 32] = acc[r][1];
        if (tx < 11) orow[tx + 64] = acc[r][2];
    }
}

// ---------------- K4: fused span pipeline, double-buffered ----------------
__global__ void span_fused(const float* __restrict__ sW2, const float* __restrict__ sb2,
                           const float* __restrict__ sW3, const float* __restrict__ sb3,
                           float* __restrict__ outF) {
    __shared__ __align__(16) float As[2][BM][17];
    __shared__ __align__(16) float Ws[2][16][152];
    __shared__ int rowS[BM], rowE[BM], wOff[BM];
    __shared__ float b2s[152];
    __shared__ float W3s[456];
    int m0 = blockIdx.x * BM;
    int tx = threadIdx.x, ty = threadIdx.y, tid = ty * 32 + tx;
    const float2 z2 = make_float2(0.f, 0.f);

    if (tid < BM) {
        int gm = m0 + tid;
        int b = gm / NS, i = gm % NS, s, e, w;
        span_decode(i, s, e, w);
        rowS[tid] = (b * SS + s) * NCAT;
        rowE[tid] = (b * SS + e) * NCAT + 150;
        wOff[tid] = w * HID;
    }
    for (int c = tid; c < 150; c += 256) b2s[c] = sb2[c];
    for (int c = tid; c < 450; c += 256) W3s[c] = sW3[c];
    if (tid < 3) W3s[450 + tid] = sb3[tid];
    __syncthreads();

    // preload tile 0
    {
        int idx = tid;
#pragma unroll
        for (int i = 0; i < 2; ++i, idx += 256) {
            int r = idx >> 4, kk = idx & 15;
            As[0][r][kk] = fmaxf(g_XH[rowS[r] + kk] + g_XH[rowE[r] + kk] + g_WEs[wOff[r] + kk], 0.f);
        }
        idx = tid;
#pragma unroll
        for (int i = 0; i < 10; ++i, idx += 256)
            if (idx < 2432) {
                int kk = idx / 152, c = idx % 152;
                Ws[0][kk][c] = (c < 150) ? sW2[(size_t)kk * HID + c] : 0.f;
            }
    }
    __syncthreads();

    float2 acc[4][3];
#pragma unroll
    for (int r = 0; r < 4; ++r)
#pragma unroll
        for (int t = 0; t < 3; ++t) acc[r][t] = z2;

    const int NT = 10;   // ceil(150/16)
    for (int t = 0; t < NT; ++t) {
        int buf = t & 1;
        float ar[2]; float wr[10];
        bool hasNext = (t + 1) < NT;
        if (hasNext) {
            int k0 = (t + 1) * 16;
            int idx = tid;
#pragma unroll
            for (int i = 0; i < 2; ++i, idx += 256) {
                int r = idx >> 4, gk = k0 + (idx & 15);
                ar[i] = (gk < HID)
                    ? fmaxf(g_XH[rowS[r] + gk] + g_XH[rowE[r] + gk] + g_WEs[wOff[r] + gk], 0.f)
                    : 0.f;
            }
            idx = tid;
#pragma unroll
            for (int i = 0; i < 10; ++i, idx += 256)
                if (idx < 2432) {
                    int kk = idx / 152, c = idx % 152, gk = k0 + kk;
                    wr[i] = (c < 150 && gk < HID) ? sW2[(size_t)gk * HID + c] : 0.f;
                }
        }
#pragma unroll
        for (int kk = 0; kk < 16; ++kk) {
            const float2* wp = reinterpret_cast<const float2*>(&Ws[buf][kk][0]);
            float2 w0 = wp[tx], w1 = wp[tx + 32];
            float2 w2 = (tx < 11) ? wp[tx + 64] : z2;
            float a[4];
#pragma unroll
            for (int r = 0; r < 4; ++r) a[r] = As[buf][ty + 8 * r][kk];
#pragma unroll
            for (int r = 0; r < 4; ++r) {
                float2 ad = make_float2(a[r], a[r]);
                acc[r][0] = ffma2(ad, w0, acc[r][0]);
                acc[r][1] = ffma2(ad, w1, acc[r][1]);
                acc[r][2] = ffma2(ad, w2, acc[r][2]);
            }
        }
        if (hasNext) {
            int nb = buf ^ 1;
            int idx = tid;
#pragma unroll
            for (int i = 0; i < 2; ++i, idx += 256)
                As[nb][idx >> 4][idx & 15] = ar[i];
            idx = tid;
#pragma unroll
            for (int i = 0; i < 10; ++i, idx += 256)
                if (idx < 2432) Ws[nb][idx / 152][idx % 152] = wr[i];
        }
        __syncthreads();
    }

#pragma unroll
    for (int rr = 0; rr < 4; ++rr) {
        int gm = m0 + ty + 8 * rr;
        float p0 = 0.f, p1 = 0.f, p2 = 0.f;
#pragma unroll
        for (int t = 0; t < 3; ++t) {
            int c0 = 2 * tx + 64 * t, c1 = c0 + 1;
            if (c0 < 150) {
                float v = fmaxf(acc[rr][t].x + b2s[c0], 0.f);
                p0 += v * W3s[c0 * 3 + 0]; p1 += v * W3s[c0 * 3 + 1]; p2 += v * W3s[c0 * 3 + 2];
            }
            if (c1 < 150) {
                float v = fmaxf(acc[rr][t].y + b2s[c1], 0.f);
                p0 += v * W3s[c1 * 3 + 0]; p1 += v * W3s[c1 * 3 + 1]; p2 += v * W3s[c1 * 3 + 2];
            }
        }
#pragma unroll
        for (int off = 16; off; off >>= 1) {
            p0 += __shfl_xor_sync(0xffffffffu, p0, off);
            p1 += __shfl_xor_sync(0xffffffffu, p1, off);
            p2 += __shfl_xor_sync(0xffffffffu, p2, off);
        }
        if (tx == 0) {
            float a0 = p0 + W3s[450], a1 = p1 + W3s[451], a2 = p2 + W3s[452];
            float m = fmaxf(a0, fmaxf(a1, a2));
            float e0 = expf(a0 - m), e1 = expf(a1 - m), e2 = expf(a2 - m);
            float inv = 1.f / (e0 + e1 + e2);
            float* o = outF + OUT_SPANS + (size_t)gm * 3;
            o[0] = e0 * inv; o[1] = e1 * inv; o[2] = e2 * inv;
            int b = gm / NS, i = gm % NS;
            g_probA[b * 1024 + i] = e1 * inv;
            g_probO[b * 1024 + i] = e2 * inv;
        }
    }
}

// ---------------- K5: top-64 per (batch, class), 1024 threads ----------------
__global__ void topk_kernel(float* __restrict__ outF) {
    __shared__ float v[1024];
    __shared__ int   id[1024];
    int bx = blockIdx.x;
    int b = bx >> 1, cls = bx & 1;
    const float* src = cls ? g_probO : g_probA;
    int i = threadIdx.x;
    v[i] = (i < NS) ? src[b * 1024 + i] : -FLT_MAX;
    id[i] = i;
    __syncthreads();
    for (int k = 2; k <= 1024; k <<= 1) {
        for (int j = k >> 1; j > 0; j >>= 1) {
            int ixj = i ^ j;
            if (ixj > i) {
                float va = v[i], vb = v[ixj];
                int ia = id[i], ib = id[ixj];
                bool bBefore = (vb > va) || (vb == va && ib < ia);
                bool dirUp = ((i & k) == 0);
                if (bBefore == dirUp) {
                    v[i] = vb; v[ixj] = va;
                    id[i] = ib; id[ixj] = ia;
                }
            }
            __syncthreads();
        }
    }
    if (i < NZ) {
        int idx = id[i];
        if (cls == 0) {
            g_tIdx[b * NZ + i] = idx;
            outF[OUT_TIDX + b * NZ + i] = (float)idx;
        } else {
            g_oIdx[b * NZ + i] = idx;
            outF[OUT_OIDX + b * NZ + i] = (float)idx;
        }
    }
}

// ---------------- K6: per-(b,i) target/opinion projected rows ----------------
__global__ void pair_tables() {
    int blk = blockIdx.x;
    int which = blk >> 9;
    int bi = blk & 511;
    int b = bi >> 6;
    int span = which ? g_oIdx[bi] : g_tIdx[bi];
    int s, e, w; span_decode(span, s, e, w);
    int c = threadIdx.x;
    const float* row_s = g_XH + (size_t)(b * SS + s) * NCAT;
    const float* row_e = g_XH + (size_t)(b * SS + e) * NCAT;
    if (c < HID) {
        if (!which)
            g_T[bi * HID + c] = row_s[300 + c] + row_e[450 + c] + g_WEt[w * HID + c];
        else
            g_O[bi * HID + c] = row_s[600 + c] + row_e[750 + c] + g_WEo[w * HID + c];
    }
    if (c == 0) {
        if (!which) { g_tS[bi] = s; g_tE[bi] = e; }
        else        { g_oS[bi] = s; g_oE[bi] = e; }
    }
}

// ---------------- K7: fused pair pipeline, double-buffered ----------------
__global__ void pair_fused(const float* __restrict__ pW2, const float* __restrict__ pb2,
                           const float* __restrict__ pW3, const float* __restrict__ pb3,
                           float* __restrict__ outF) {
    __shared__ __align__(16) float As[2][BM][17];
    __shared__ __align__(16) float Ws[2][16][152];
    __shared__ float Trow[152];
    __shared__ int oBase[BM], dOff[BM];
    __shared__ float b2s[152];
    __shared__ float W3s[608];
    int p0 = blockIdx.x * BM;            // 32 pairs: fixed (b,i), 32 consecutive j
    int b = p0 >> 12;
    int i = (p0 >> 6) & 63;
    int bi = b * NZ + i;
    int tx = threadIdx.x, ty = threadIdx.y, tid = ty * 32 + tx;
    const float2 z2 = make_float2(0.f, 0.f);

    if (tid < BM) {
        int j = (p0 & 63) + tid;
        int bj = b * NZ + j;
        oBase[tid] = bj * HID;
        int dist = min(abs(g_tE[bi] - g_oS[bj]), abs(g_tS[bi] - g_oE[bj]));
        int bucket = dist >= 64 ? 9 : dist >= 32 ? 8 : dist >= 16 ? 7 : dist >= 8 ? 6 : dist >= 5 ? 5 : dist;
        dOff[tid] = bucket * HID;
    }
    if (tid < 150) Trow[tid] = g_T[bi * HID + tid];
    for (int c = tid; c < 150; c += 256) b2s[c] = pb2[c];
    for (int c = tid; c < 600; c += 256) W3s[c] = pW3[c];
    if (tid < 4) W3s[600 + tid] = pb3[tid];
    __syncthreads();

    // preload tile 0
    {
        int idx = tid;
#pragma unroll
        for (int i2 = 0; i2 < 2; ++i2, idx += 256) {
            int r = idx >> 4, kk = idx & 15;
            As[0][r][kk] = fmaxf(Trow[kk] + g_O[oBase[r] + kk] + g_Dtab[dOff[r] + kk], 0.f);
        }
        idx = tid;
#pragma unroll
        for (int i2 = 0; i2 < 10; ++i2, idx += 256)
            if (idx < 2432) {
                int kk = idx / 152, c = idx % 152;
                Ws[0][kk][c] = (c < 150) ? pW2[(size_t)kk * HID + c] : 0.f;
            }
    }
    __syncthreads();

    float2 acc[4][3];
#pragma unroll
    for (int r = 0; r < 4; ++r)
#pragma unroll
        for (int t = 0; t < 3; ++t) acc[r][t] = z2;

    const int NT = 10;
    for (int t = 0; t < NT; ++t) {
        int buf = t & 1;
        float ar[2]; float wr[10];
        bool hasNext = (t + 1) < NT;
        if (hasNext) {
            int k0 = (t + 1) * 16;
            int idx = tid;
#pragma unroll
            for (int i2 = 0; i2 < 2; ++i2, idx += 256) {
                int r = idx >> 4, gk = k0 + (idx & 15);
                ar[i2] = (gk < HID)
                    ? fmaxf(Trow[gk] + g_O[oBase[r] + gk] + g_Dtab[dOff[r] + gk], 0.f)
                    : 0.f;
            }
            idx = tid;
#pragma unroll
            for (int i2 = 0; i2 < 10; ++i2, idx += 256)
                if (idx < 2432) {
                    int kk = idx / 152, c = idx % 152, gk = k0 + kk;
                    wr[i2] = (c < 150 && gk < HID) ? pW2[(size_t)gk * HID + c] : 0.f;
                }
        }
#pragma unroll
        for (int kk = 0; kk < 16; ++kk) {
            const float2* wp = reinterpret_cast<const float2*>(&Ws[buf][kk][0]);
            float2 w0 = wp[tx], w1 = wp[tx + 32];
            float2 w2 = (tx < 11) ? wp[tx + 64] : z2;
            float a[4];
#pragma unroll
            for (int r = 0; r < 4; ++r) a[r] = As[buf][ty + 8 * r][kk];
#pragma unroll
            for (int r = 0; r < 4; ++r) {
                float2 ad = make_float2(a[r], a[r]);
                acc[r][0] = ffma2(ad, w0, acc[r][0]);
                acc[r][1] = ffma2(ad, w1, acc[r][1]);
                acc[r][2] = ffma2(ad, w2, acc[r][2]);
            }
        }
        if (hasNext) {
            int nb = buf ^ 1;
            int idx = tid;
#pragma unroll
            for (int i2 = 0; i2 < 2; ++i2, idx += 256)
                As[nb][idx >> 4][idx & 15] = ar[i2];
            idx = tid;
#pragma unroll
            for (int i2 = 0; i2 < 10; ++i2, idx += 256)
                if (idx < 2432) Ws[nb][idx / 152][idx % 152] = wr[i2];
        }
        __syncthreads();
    }

#pragma unroll
    for (int rr = 0; rr < 4; ++rr) {
        int gm = p0 + ty + 8 * rr;
        float q0 = 0.f, q1 = 0.f, q2 = 0.f, q3 = 0.f;
#pragma unroll
        for (int t = 0; t < 3; ++t) {
            int c0 = 2 * tx + 64 * t, c1 = c0 + 1;
            if (c0 < 150) {
                float v = fmaxf(acc[rr][t].x + b2s[c0], 0.f);
                q0 += v * W3s[c0 * 4 + 0]; q1 += v * W3s[c0 * 4 + 1];
                q2 += v * W3s[c0 * 4 + 2]; q3 += v * W3s[c0 * 4 + 3];
            }
            if (c1 < 150) {
                float v = fmaxf(acc[rr][t].y + b2s[c1], 0.f);
                q0 += v * W3s[c1 * 4 + 0]; q1 += v * W3s[c1 * 4 + 1];
                q2 += v * W3s[c1 * 4 + 2]; q3 += v * W3s[c1 * 4 + 3];
            }
        }
#pragma unroll
        for (int off = 16; off; off >>= 1) {
            q0 += __shfl_xor_sync(0xffffffffu, q0, off);
            q1 += __shfl_xor_sync(0xffffffffu, q1, off);
            q2 += __shfl_xor_sync(0xffffffffu, q2, off);
            q3 += __shfl_xor_sync(0xffffffffu, q3, off);
        }
        if (tx == 0) {
            float a0 = q0 + W3s[600], a1 = q1 + W3s[601], a2 = q2 + W3s[602], a3 = q3 + W3s[603];
            float m = fmaxf(fmaxf(a0, a1), fmaxf(a2, a3));
            float e0 = expf(a0 - m), e1 = expf(a1 - m), e2 = expf(a2 - m), e3 = expf(a3 - m);
            float inv = 1.f / (e0 + e1 + e2 + e3);
            float* o = outF + OUT_CAND + (size_t)gm * 4;
            o[0] = e0 * inv; o[1] = e1 * inv; o[2] = e2 * inv; o[3] = e3 * inv;
        }
    }
}

// ---------------- launch ----------------
extern "C" void kernel_launch(void* const* d_in, const int* in_sizes, int n_in,
                              void* d_out, int out_size) {
    const float* x        = (const float*)d_in[0];
    const float* width_e  = (const float*)d_in[1];
    const float* sW1      = (const float*)d_in[2];
    const float* sb1      = (const float*)d_in[3];
    const float* sW2      = (const float*)d_in[4];
    const float* sb2      = (const float*)d_in[5];
    const float* sW3      = (const float*)d_in[6];
    const float* sb3      = (const float*)d_in[7];
    const float* dist_e   = (const float*)d_in[8];
    const float* pW1      = (const float*)d_in[9];
    const float* pb1      = (const float*)d_in[10];
    const float* pW2      = (const float*)d_in[11];
    const float* pb2      = (const float*)d_in[12];
    const float* pW3      = (const float*)d_in[13];
    const float* pb3      = (const float*)d_in[14];
    float* outF = (float*)d_out;

    dim3 blk(32, 8);

    tables_kernel<<<34, 160>>>(width_e, sW1, sb1, dist_e, pW1, pb1);
    proj_gemm<<<dim3(BB * SS / BM, 6), blk>>>(x, sW1, pW1);
    span_fused<<<NSPANS_TOT / BM, blk>>>(sW2, sb2, sW3, sb3, outF);
    topk_kernel<<<BB * 2, 1024>>>(outF);
    pair_tables<<<2 * BB * NZ, 160>>>();
    pair_fused<<<NPAIRS_TOT / BM, blk>>>(pW2, pb2, pW3, pb3, outF);
}

// round 6
// speedup vs baseline: 1.8794x; 1.0998x over previous
#include <cuda_runtime.h>
#include <math.h>
#include <float.h>

// ---------------- problem constants ----------------
#define BB 8
#define SS 128
#define HH 768
#define NS 996
#define HID 150
#define NZ 64
#define NPAIR (NZ*NZ)
#define NSPANS_TOT (BB*NS)      // 7968 = 249*32
#define NPAIRS_TOT (BB*NPAIR)   // 32768 = 1024*32
#define NCAT 900
#define BM 32
#define WSM_ROWS 160            // 150 padded to 10 k-tiles of 16
#define WSM_PITCH 152
#define WSM_FLOATS (WSM_ROWS*WSM_PITCH)   // 24320
#define WSM_BYTES (WSM_FLOATS*4)          // 97280

#define NTILES_SPAN (NSPANS_TOT/BM)   // 249
#define NTILES_PAIR (NPAIRS_TOT/BM)   // 1024

// output regions (floats)
#define OUT_SPANS 0
#define OUT_CAND  (BB*NS*3)                 // 23904
#define OUT_TIDX  (OUT_CAND + BB*NPAIR*4)   // 154976
#define OUT_OIDX  (OUT_TIDX + BB*NZ)        // 155488

// ---------------- scratch ----------------
__device__ float g_XH[BB * SS * NCAT];
__device__ float g_WEs[8 * HID];
__device__ float g_WEt[8 * HID];
__device__ float g_WEo[8 * HID];
__device__ float g_Dtab[10 * HID];
__device__ float g_probA[BB * 1024];
__device__ float g_probO[BB * 1024];
__device__ int   g_tIdx[BB * NZ];
__device__ int   g_oIdx[BB * NZ];
__device__ int   g_tS[BB * NZ], g_tE[BB * NZ], g_oS[BB * NZ], g_oE[BB * NZ];
__device__ float g_T[BB * NZ * HID];
__device__ float g_O[BB * NZ * HID];

// ---------------- packed fp32x2 FMA (Blackwell) ----------------
union F2U { float2 f; unsigned long long u; };
static __device__ __forceinline__ float2 ffma2(float2 a, float2 b, float2 c) {
    F2U A, B, C, D; A.f = a; B.f = b; C.f = c;
    asm("fma.rn.f32x2 %0, %1, %2, %3;" : "=l"(D.u) : "l"(A.u), "l"(B.u), "l"(C.u));
    return D.f;
}

__device__ __forceinline__ void span_decode(int i, int& s, int& e, int& w) {
    int off = 0;
#pragma unroll
    for (int wi = 1; wi <= 8; ++wi) {
        int cnt = SS - wi + 1;
        if (i < off + cnt) { s = i - off; e = s + wi - 1; w = wi - 1; return; }
        off += cnt;
    }
    s = 0; e = 0; w = 0;
}

// ---------------- K2: tiny tables ----------------
__global__ void tables_kernel(const float* __restrict__ width_emb,
                              const float* __restrict__ sW1, const float* __restrict__ sb1,
                              const float* __restrict__ dist_emb,
                              const float* __restrict__ pW1, const float* __restrict__ pb1) {
    int blk = blockIdx.x;
    int n = threadIdx.x;
    if (n >= HID) return;
    if (blk < 8) {
        float acc = sb1[n];
        for (int k = 0; k < 20; ++k) acc += width_emb[blk * 20 + k] * sW1[(1536 + k) * HID + n];
        g_WEs[blk * HID + n] = acc;
    } else if (blk < 16) {
        int r = blk - 8; float acc = 0.f;
        for (int k = 0; k < 20; ++k) acc += width_emb[r * 20 + k] * pW1[(1536 + k) * HID + n];
        g_WEt[r * HID + n] = acc;
    } else if (blk < 24) {
        int r = blk - 16; float acc = 0.f;
        for (int k = 0; k < 20; ++k) acc += width_emb[r * 20 + k] * pW1[(3092 + k) * HID + n];
        g_WEo[r * HID + n] = acc;
    } else {
        int r = blk - 24; float acc = pb1[n];
        for (int k = 0; k < 128; ++k) acc += dist_emb[r * 128 + k] * pW1[(3112 + k) * HID + n];
        g_Dtab[r * HID + n] = acc;
    }
}

// ---------------- K3: XH = x @ slab-weights, double-buffered ----------------
__global__ void proj_gemm(const float* __restrict__ A,
                          const float* __restrict__ sW1, const float* __restrict__ pW1) {
    __shared__ __align__(16) float As[2][BM][17];
    __shared__ __align__(16) float Ws[2][16][152];
    int m0 = blockIdx.x * BM;
    int slab = blockIdx.y;
    const float* src;
    switch (slab) {
        case 0: src = sW1; break;
        case 1: src = sW1 + 768 * HID; break;
        case 2: src = pW1; break;
        case 3: src = pW1 + 768 * HID; break;
        case 4: src = pW1 + 1556 * HID; break;
        default: src = pW1 + 2324 * HID; break;
    }
    int tx = threadIdx.x, ty = threadIdx.y, tid = ty * 32 + tx;
    const float2 z2 = make_float2(0.f, 0.f);
    float2 acc[4][3];
#pragma unroll
    for (int r = 0; r < 4; ++r)
#pragma unroll
        for (int t = 0; t < 3; ++t) acc[r][t] = z2;

    {
        int idx = tid;
#pragma unroll
        for (int i = 0; i < 2; ++i, idx += 256)
            As[0][idx >> 4][idx & 15] = A[(size_t)(m0 + (idx >> 4)) * HH + (idx & 15)];
        idx = tid;
#pragma unroll
        for (int i = 0; i < 10; ++i, idx += 256)
            if (idx < 2432) {
                int kk = idx / 152, c = idx % 152;
                Ws[0][kk][c] = (c < 150) ? src[(size_t)kk * HID + c] : 0.f;
            }
    }
    __syncthreads();

    const int NT = HH / 16;
    for (int t = 0; t < NT; ++t) {
        int buf = t & 1;
        float ar[2]; float wr[10];
        bool hasNext = (t + 1) < NT;
        if (hasNext) {
            int k0 = (t + 1) * 16;
            int idx = tid;
#pragma unroll
            for (int i = 0; i < 2; ++i, idx += 256)
                ar[i] = A[(size_t)(m0 + (idx >> 4)) * HH + k0 + (idx & 15)];
            idx = tid;
#pragma unroll
            for (int i = 0; i < 10; ++i, idx += 256)
                if (idx < 2432) {
                    int kk = idx / 152, c = idx % 152;
                    wr[i] = (c < 150) ? src[(size_t)(k0 + kk) * HID + c] : 0.f;
                }
        }
#pragma unroll
        for (int kk = 0; kk < 16; ++kk) {
            const float2* wp = reinterpret_cast<const float2*>(&Ws[buf][kk][0]);
            float2 w0 = wp[tx], w1 = wp[tx + 32];
            float2 w2 = (tx < 11) ? wp[tx + 64] : z2;
            float a[4];
#pragma unroll
            for (int r = 0; r < 4; ++r) a[r] = As[buf][ty + 8 * r][kk];
#pragma unroll
            for (int r = 0; r < 4; ++r) {
                float2 ad = make_float2(a[r], a[r]);
                acc[r][0] = ffma2(ad, w0, acc[r][0]);
                acc[r][1] = ffma2(ad, w1, acc[r][1]);
                acc[r][2] = ffma2(ad, w2, acc[r][2]);
            }
        }
        if (hasNext) {
            int nb = buf ^ 1;
            int idx = tid;
#pragma unroll
            for (int i = 0; i < 2; ++i, idx += 256)
                As[nb][idx >> 4][idx & 15] = ar[i];
            idx = tid;
#pragma unroll
            for (int i = 0; i < 10; ++i, idx += 256)
                if (idx < 2432) Ws[nb][idx / 152][idx % 152] = wr[i];
        }
        __syncthreads();
    }
#pragma unroll
    for (int r = 0; r < 4; ++r) {
        int gm = m0 + ty + 8 * r;
        float2* orow = reinterpret_cast<float2*>(g_XH + (size_t)gm * NCAT + slab * HID);
        orow[tx] = acc[r][0];
        orow[tx + 32] = acc[r][1];
        if (tx < 11) orow[tx + 64] = acc[r][2];
    }
}

// ---------------- K4: fused span pipeline, weight-resident ----------------
__global__ void span_fused(const float* __restrict__ sW2, const float* __restrict__ sb2,
                           const float* __restrict__ sW3, const float* __restrict__ sb3,
                           float* __restrict__ outF) {
    extern __shared__ __align__(16) float Wsm[];   // [WSM_ROWS][WSM_PITCH], zero-padded
    __shared__ __align__(16) float As[2][BM][17];
    __shared__ int rowS[BM], rowE[BM], wOff[BM];
    __shared__ float b2s[152];
    __shared__ float W3s[456];
    int tx = threadIdx.x, ty = threadIdx.y, tid = ty * 32 + tx;
    const float2 z2 = make_float2(0.f, 0.f);

    for (int idx = tid; idx < WSM_FLOATS; idx += 256) {
        int k = idx / WSM_PITCH, c = idx % WSM_PITCH;
        Wsm[idx] = (k < HID && c < HID) ? sW2[(size_t)k * HID + c] : 0.f;
    }
    for (int c = tid; c < 150; c += 256) b2s[c] = sb2[c];
    for (int c = tid; c < 450; c += 256) W3s[c] = sW3[c];
    if (tid < 3) W3s[450 + tid] = sb3[tid];
    __syncthreads();

    for (int tile = blockIdx.x; tile < NTILES_SPAN; tile += gridDim.x) {
        int m0 = tile * BM;
        if (tid < BM) {
            int gm = m0 + tid;
            int b = gm / NS, i = gm % NS, s, e, w;
            span_decode(i, s, e, w);
            rowS[tid] = (b * SS + s) * NCAT;
            rowE[tid] = (b * SS + e) * NCAT + 150;
            wOff[tid] = w * HID;
        }
        __syncthreads();
        {
            int idx = tid;
#pragma unroll
            for (int i = 0; i < 2; ++i, idx += 256) {
                int r = idx >> 4, kk = idx & 15;
                As[0][r][kk] = fmaxf(g_XH[rowS[r] + kk] + g_XH[rowE[r] + kk] + g_WEs[wOff[r] + kk], 0.f);
            }
        }
        __syncthreads();

        float2 acc[4][3];
#pragma unroll
        for (int r = 0; r < 4; ++r)
#pragma unroll
            for (int t = 0; t < 3; ++t) acc[r][t] = z2;

        for (int t = 0; t < 10; ++t) {
            int buf = t & 1;
            float ar[2];
            bool hasNext = (t + 1) < 10;
            if (hasNext) {
                int k0 = (t + 1) * 16;
                int idx = tid;
#pragma unroll
                for (int i = 0; i < 2; ++i, idx += 256) {
                    int r = idx >> 4, gk = k0 + (idx & 15);
                    ar[i] = (gk < HID)
                        ? fmaxf(g_XH[rowS[r] + gk] + g_XH[rowE[r] + gk] + g_WEs[wOff[r] + gk], 0.f)
                        : 0.f;
                }
            }
#pragma unroll
            for (int kk = 0; kk < 16; ++kk) {
                const float2* wp = reinterpret_cast<const float2*>(&Wsm[(t * 16 + kk) * WSM_PITCH]);
                float2 w0 = wp[tx], w1 = wp[tx + 32];
                float2 w2 = (tx < 11) ? wp[tx + 64] : z2;
                float a[4];
#pragma unroll
                for (int r = 0; r < 4; ++r) a[r] = As[buf][ty + 8 * r][kk];
#pragma unroll
                for (int r = 0; r < 4; ++r) {
                    float2 ad = make_float2(a[r], a[r]);
                    acc[r][0] = ffma2(ad, w0, acc[r][0]);
                    acc[r][1] = ffma2(ad, w1, acc[r][1]);
                    acc[r][2] = ffma2(ad, w2, acc[r][2]);
                }
            }
            if (hasNext) {
                int nb = buf ^ 1;
                int idx = tid;
#pragma unroll
                for (int i = 0; i < 2; ++i, idx += 256)
                    As[nb][idx >> 4][idx & 15] = ar[i];
            }
            __syncthreads();
        }

#pragma unroll
        for (int rr = 0; rr < 4; ++rr) {
            int gm = m0 + ty + 8 * rr;
            float p0 = 0.f, p1 = 0.f, p2 = 0.f;
#pragma unroll
            for (int t = 0; t < 3; ++t) {
                int c0 = 2 * tx + 64 * t, c1 = c0 + 1;
                if (c0 < 150) {
                    float v = fmaxf(acc[rr][t].x + b2s[c0], 0.f);
                    p0 += v * W3s[c0 * 3 + 0]; p1 += v * W3s[c0 * 3 + 1]; p2 += v * W3s[c0 * 3 + 2];
                }
                if (c1 < 150) {
                    float v = fmaxf(acc[rr][t].y + b2s[c1], 0.f);
                    p0 += v * W3s[c1 * 3 + 0]; p1 += v * W3s[c1 * 3 + 1]; p2 += v * W3s[c1 * 3 + 2];
                }
            }
#pragma unroll
            for (int off = 16; off; off >>= 1) {
                p0 += __shfl_xor_sync(0xffffffffu, p0, off);
                p1 += __shfl_xor_sync(0xffffffffu, p1, off);
                p2 += __shfl_xor_sync(0xffffffffu, p2, off);
            }
            if (tx == 0) {
                float a0 = p0 + W3s[450], a1 = p1 + W3s[451], a2 = p2 + W3s[452];
                float m = fmaxf(a0, fmaxf(a1, a2));
                float e0 = expf(a0 - m), e1 = expf(a1 - m), e2 = expf(a2 - m);
                float inv = 1.f / (e0 + e1 + e2);
                float* o = outF + OUT_SPANS + (size_t)gm * 3;
                o[0] = e0 * inv; o[1] = e1 * inv; o[2] = e2 * inv;
                int b = gm / NS, i = gm % NS;
                g_probA[b * 1024 + i] = e1 * inv;
                g_probO[b * 1024 + i] = e2 * inv;
            }
        }
        __syncthreads();
    }
}

// ---------------- K5: top-64 per (batch, class), 1024 threads ----------------
__global__ void topk_kernel(float* __restrict__ outF) {
    __shared__ float v[1024];
    __shared__ int   id[1024];
    int bx = blockIdx.x;
    int b = bx >> 1, cls = bx & 1;
    const float* src = cls ? g_probO : g_probA;
    int i = threadIdx.x;
    v[i] = (i < NS) ? src[b * 1024 + i] : -FLT_MAX;
    id[i] = i;
    __syncthreads();
    for (int k = 2; k <= 1024; k <<= 1) {
        for (int j = k >> 1; j > 0; j >>= 1) {
            int ixj = i ^ j;
            if (ixj > i) {
                float va = v[i], vb = v[ixj];
                int ia = id[i], ib = id[ixj];
                bool bBefore = (vb > va) || (vb == va && ib < ia);
                bool dirUp = ((i & k) == 0);
                if (bBefore == dirUp) {
                    v[i] = vb; v[ixj] = va;
                    id[i] = ib; id[ixj] = ia;
                }
            }
            __syncthreads();
        }
    }
    if (i < NZ) {
        int idx = id[i];
        if (cls == 0) {
            g_tIdx[b * NZ + i] = idx;
            outF[OUT_TIDX + b * NZ + i] = (float)idx;
        } else {
            g_oIdx[b * NZ + i] = idx;
            outF[OUT_OIDX + b * NZ + i] = (float)idx;
        }
    }
}

// ---------------- K6: per-(b,i) target/opinion projected rows ----------------
__global__ void pair_tables() {
    int blk = blockIdx.x;
    int which = blk >> 9;
    int bi = blk & 511;
    int b = bi >> 6;
    int span = which ? g_oIdx[bi] : g_tIdx[bi];
    int s, e, w; span_decode(span, s, e, w);
    int c = threadIdx.x;
    const float* row_s = g_XH + (size_t)(b * SS + s) * NCAT;
    const float* row_e = g_XH + (size_t)(b * SS + e) * NCAT;
    if (c < HID) {
        if (!which)
            g_T[bi * HID + c] = row_s[300 + c] + row_e[450 + c] + g_WEt[w * HID + c];
        else
            g_O[bi * HID + c] = row_s[600 + c] + row_e[750 + c] + g_WEo[w * HID + c];
    }
    if (c == 0) {
        if (!which) { g_tS[bi] = s; g_tE[bi] = e; }
        else        { g_oS[bi] = s; g_oE[bi] = e; }
    }
}

// ---------------- K7: fused pair pipeline, weight-resident ----------------
__global__ void pair_fused(const float* __restrict__ pW2, const float* __restrict__ pb2,
                           const float* __restrict__ pW3, const float* __restrict__ pb3,
                           float* __restrict__ outF) {
    extern __shared__ __align__(16) float Wsm[];
    __shared__ __align__(16) float As[2][BM][17];
    __shared__ float Trow[152];
    __shared__ int oBase[BM], dOff[BM];
    __shared__ float b2s[152];
    __shared__ float W3s[608];
    int tx = threadIdx.x, ty = threadIdx.y, tid = ty * 32 + tx;
    const float2 z2 = make_float2(0.f, 0.f);

    for (int idx = tid; idx < WSM_FLOATS; idx += 256) {
        int k = idx / WSM_PITCH, c = idx % WSM_PITCH;
        Wsm[idx] = (k < HID && c < HID) ? pW2[(size_t)k * HID + c] : 0.f;
    }
    for (int c = tid; c < 150; c += 256) b2s[c] = pb2[c];
    for (int c = tid; c < 600; c += 256) W3s[c] = pW3[c];
    if (tid < 4) W3s[600 + tid] = pb3[tid];
    __syncthreads();

    for (int tile = blockIdx.x; tile < NTILES_PAIR; tile += gridDim.x) {
        int p0 = tile * BM;
        int b = p0 >> 12;
        int i = (p0 >> 6) & 63;
        int bi = b * NZ + i;
        if (tid < BM) {
            int j = (p0 & 63) + tid;
            int bj = b * NZ + j;
            oBase[tid] = bj * HID;
            int dist = min(abs(g_tE[bi] - g_oS[bj]), abs(g_tS[bi] - g_oE[bj]));
            int bucket = dist >= 64 ? 9 : dist >= 32 ? 8 : dist >= 16 ? 7 : dist >= 8 ? 6 : dist >= 5 ? 5 : dist;
            dOff[tid] = bucket * HID;
        }
        if (tid < 150) Trow[tid] = g_T[bi * HID + tid];
        __syncthreads();
        {
            int idx = tid;
#pragma unroll
            for (int i2 = 0; i2 < 2; ++i2, idx += 256) {
                int r = idx >> 4, kk = idx & 15;
                As[0][r][kk] = fmaxf(Trow[kk] + g_O[oBase[r] + kk] + g_Dtab[dOff[r] + kk], 0.f);
            }
        }
        __syncthreads();

        float2 acc[4][3];
#pragma unroll
        for (int r = 0; r < 4; ++r)
#pragma unroll
            for (int t = 0; t < 3; ++t) acc[r][t] = z2;

        for (int t = 0; t < 10; ++t) {
            int buf = t & 1;
            float ar[2];
            bool hasNext = (t + 1) < 10;
            if (hasNext) {
                int k0 = (t + 1) * 16;
                int idx = tid;
#pragma unroll
                for (int i2 = 0; i2 < 2; ++i2, idx += 256) {
                    int r = idx >> 4, gk = k0 + (idx & 15);
                    ar[i2] = (gk < HID)
                        ? fmaxf(Trow[gk] + g_O[oBase[r] + gk] + g_Dtab[dOff[r] + gk], 0.f)
                        : 0.f;
                }
            }
#pragma unroll
            for (int kk = 0; kk < 16; ++kk) {
                const float2* wp = reinterpret_cast<const float2*>(&Wsm[(t * 16 + kk) * WSM_PITCH]);
                float2 w0 = wp[tx], w1 = wp[tx + 32];
                float2 w2 = (tx < 11) ? wp[tx + 64] : z2;
                float a[4];
#pragma unroll
                for (int r = 0; r < 4; ++r) a[r] = As[buf][ty + 8 * r][kk];
#pragma unroll
                for (int r = 0; r < 4; ++r) {
                    float2 ad = make_float2(a[r], a[r]);
                    acc[r][0] = ffma2(ad, w0, acc[r][0]);
                    acc[r][1] = ffma2(ad, w1, acc[r][1]);
                    acc[r][2] = ffma2(ad, w2, acc[r][2]);
                }
            }
            if (hasNext) {
                int nb = buf ^ 1;
                int idx = tid;
#pragma unroll
                for (int i2 = 0; i2 < 2; ++i2, idx += 256)
                    As[nb][idx >> 4][idx & 15] = ar[i2];
            }
            __syncthreads();
        }

#pragma unroll
        for (int rr = 0; rr < 4; ++rr) {
            int gm = p0 + ty + 8 * rr;
            float q0 = 0.f, q1 = 0.f, q2 = 0.f, q3 = 0.f;
#pragma unroll
            for (int t = 0; t < 3; ++t) {
                int c0 = 2 * tx + 64 * t, c1 = c0 + 1;
                if (c0 < 150) {
                    float v = fmaxf(acc[rr][t].x + b2s[c0], 0.f);
                    q0 += v * W3s[c0 * 4 + 0]; q1 += v * W3s[c0 * 4 + 1];
                    q2 += v * W3s[c0 * 4 + 2]; q3 += v * W3s[c0 * 4 + 3];
                }
                if (c1 < 150) {
                    float v = fmaxf(acc[rr][t].y + b2s[c1], 0.f);
                    q0 += v * W3s[c1 * 4 + 0]; q1 += v * W3s[c1 * 4 + 1];
                    q2 += v * W3s[c1 * 4 + 2]; q3 += v * W3s[c1 * 4 + 3];
                }
            }
#pragma unroll
            for (int off = 16; off; off >>= 1) {
                q0 += __shfl_xor_sync(0xffffffffu, q0, off);
                q1 += __shfl_xor_sync(0xffffffffu, q1, off);
                q2 += __shfl_xor_sync(0xffffffffu, q2, off);
                q3 += __shfl_xor_sync(0xffffffffu, q3, off);
            }
            if (tx == 0) {
                float a0 = q0 + W3s[600], a1 = q1 + W3s[601], a2 = q2 + W3s[602], a3 = q3 + W3s[603];
                float m = fmaxf(fmaxf(a0, a1), fmaxf(a2, a3));
                float e0 = expf(a0 - m), e1 = expf(a1 - m), e2 = expf(a2 - m), e3 = expf(a3 - m);
                float inv = 1.f / (e0 + e1 + e2 + e3);
                float* o = outF + OUT_CAND + (size_t)gm * 4;
                o[0] = e0 * inv; o[1] = e1 * inv; o[2] = e2 * inv; o[3] = e3 * inv;
            }
        }
        __syncthreads();
    }
}

// ---------------- launch ----------------
extern "C" void kernel_launch(void* const* d_in, const int* in_sizes, int n_in,
                              void* d_out, int out_size) {
    const float* x        = (const float*)d_in[0];
    const float* width_e  = (const float*)d_in[1];
    const float* sW1      = (const float*)d_in[2];
    const float* sb1      = (const float*)d_in[3];
    const float* sW2      = (const float*)d_in[4];
    const float* sb2      = (const float*)d_in[5];
    const float* sW3      = (const float*)d_in[6];
    const float* sb3      = (const float*)d_in[7];
    const float* dist_e   = (const float*)d_in[8];
    const float* pW1      = (const float*)d_in[9];
    const float* pb1      = (const float*)d_in[10];
    const float* pW2      = (const float*)d_in[11];
    const float* pb2      = (const float*)d_in[12];
    const float* pW3      = (const float*)d_in[13];
    const float* pb3      = (const float*)d_in[14];
    float* outF = (float*)d_out;

    // Idempotent, host-side, non-allocating; legal under graph capture.
    cudaFuncSetAttribute(span_fused, cudaFuncAttributeMaxDynamicSharedMemorySize, WSM_BYTES);
    cudaFuncSetAttribute(pair_fused, cudaFuncAttributeMaxDynamicSharedMemorySize, WSM_BYTES);

    dim3 blk(32, 8);

    tables_kernel<<<34, 160>>>(width_e, sW1, sb1, dist_e, pW1, pb1);
    proj_gemm<<<dim3(BB * SS / BM, 6), blk>>>(x, sW1, pW1);
    span_fused<<<NTILES_SPAN, blk, WSM_BYTES>>>(sW2, sb2, sW3, sb3, outF);
    topk_kernel<<<BB * 2, 1024>>>(outF);
    pair_tables<<<2 * BB * NZ, 160>>>();
    pair_fused<<<296, blk, WSM_BYTES>>>(pW2, pb2, pW3, pb3, outF);
}